// round 3
// baseline (speedup 1.0000x reference)
#include <cuda_runtime.h>
#include <math.h>

#define MM 256
#define DD 768
#define THRESH 0.3f
#define EPSF 1e-8f

// ---------------- device scratch (no allocations allowed) ----------------
__device__ float g_nm2[MM];          // ||m_i||^2
__device__ float g_rnm[MM];          // 1/max(||m_i||, EPS)
__device__ float g_Sm[MM];           // sum(m_i)
__device__ float g_kx[MM];           // dot(m_i, x)
__device__ float g_mx[MM];           // cos(m_i, x)
__device__ float g_mask[MM];
__device__ float g_nx, g_Sx, g_cnt, g_A2;
__device__ float g_km[MM * MM];      // mem @ mem^T
__device__ float g_A1[MM];
__device__ float g_s[MM * MM];       // scalar added to row (a,i)

// ---------------- K0: per-row stats + x stats ----------------
// grid = MM+1 blocks of 256 threads. Block b<MM reduces mem row b; block MM reduces x.
__global__ void k_stats(const float* __restrict__ x, const float* __restrict__ mem) {
    int b = blockIdx.x, t = threadIdx.x;
    float s0 = 0.f, s1 = 0.f, s2 = 0.f;
    if (b < MM) {
        const float* row = mem + b * DD;
        for (int d = t; d < DD; d += 256) {
            float v = row[d], xv = x[d];
            s0 = fmaf(v, v, s0);
            s1 += v;
            s2 = fmaf(v, xv, s2);
        }
    } else {
        for (int d = t; d < DD; d += 256) {
            float xv = x[d];
            s0 = fmaf(xv, xv, s0);
            s1 += xv;
        }
    }
    __shared__ float sh[3][8];
#pragma unroll
    for (int o = 16; o; o >>= 1) {
        s0 += __shfl_down_sync(0xffffffffu, s0, o);
        s1 += __shfl_down_sync(0xffffffffu, s1, o);
        s2 += __shfl_down_sync(0xffffffffu, s2, o);
    }
    if ((t & 31) == 0) { int w = t >> 5; sh[0][w] = s0; sh[1][w] = s1; sh[2][w] = s2; }
    __syncthreads();
    if (t == 0) {
        float a = 0.f, c = 0.f, e = 0.f;
        for (int w = 0; w < 8; w++) { a += sh[0][w]; c += sh[1][w]; e += sh[2][w]; }
        if (b < MM) {
            g_nm2[b] = a;
            float nm = sqrtf(a);
            g_rnm[b] = 1.f / fmaxf(nm, EPSF);
            g_Sm[b] = c;
            g_kx[b] = e;
        } else {
            g_nx = fmaxf(sqrtf(a), EPSF);
            g_Sx = c;
        }
    }
}

// ---------------- K1: mask, cnt, A2 (one block of 256) ----------------
__global__ void k_mask_kernel() {
    int i = threadIdx.x;
    float rnx = 1.f / g_nx;
    float mx = g_kx[i] * g_rnm[i] * rnx;
    float mk = (mx > THRESH) ? 1.f : 0.f;
    g_mx[i] = mx;
    g_mask[i] = mk;
    float c0 = mk;
    float c1 = mk * g_Sm[i] * g_rnm[i];
    __shared__ float sh[2][8];
#pragma unroll
    for (int o = 16; o; o >>= 1) {
        c0 += __shfl_down_sync(0xffffffffu, c0, o);
        c1 += __shfl_down_sync(0xffffffffu, c1, o);
    }
    if ((i & 31) == 0) { int w = i >> 5; sh[0][w] = c0; sh[1][w] = c1; }
    __syncthreads();
    if (i == 0) {
        float a = 0.f, b = 0.f;
        for (int w = 0; w < 8; w++) { a += sh[0][w]; b += sh[1][w]; }
        g_cnt = a;
        g_A2 = b;
    }
}

// ---------------- K2: gram = mem @ mem^T (shared-mem tiled) ----------------
// grid (16,16) of 256-thread blocks; each block does a 16x16 output tile, K tiled by 64.
__global__ void k_gram(const float* __restrict__ mem) {
    __shared__ float sA[16][65];  // pad 65 -> conflict-free sB[tx][k]
    __shared__ float sB[16][65];
    int ti = threadIdx.x;
    int ty = ti >> 4, tx = ti & 15;
    int r0 = blockIdx.y * 16, c0 = blockIdx.x * 16;
    float acc = 0.f;
    for (int k0 = 0; k0 < DD; k0 += 64) {
#pragma unroll
        for (int q = 0; q < 4; q++) {
            int idx = ti + q * 256;
            int rr = idx >> 6, cc = idx & 63;
            sA[rr][cc] = mem[(r0 + rr) * DD + k0 + cc];
            sB[rr][cc] = mem[(c0 + rr) * DD + k0 + cc];
        }
        __syncthreads();
#pragma unroll
        for (int k = 0; k < 64; k++)
            acc = fmaf(sA[ty][k], sB[tx][k], acc);
        __syncthreads();
    }
    g_km[(r0 + ty) * MM + (c0 + tx)] = acc;
}

// ---------------- K3: A1[i] = sum_j km[i,j]*mask[j]/nm_s[j] ----------------
__global__ void k_a1() {
    int i = blockIdx.x, t = threadIdx.x;
    float v = g_km[i * MM + t] * g_mask[t] * g_rnm[t];
    __shared__ float sh[8];
#pragma unroll
    for (int o = 16; o; o >>= 1) v += __shfl_down_sync(0xffffffffu, v, o);
    if ((t & 31) == 0) sh[t >> 5] = v;
    __syncthreads();
    if (t == 0) {
        float s = 0.f;
        for (int w = 0; w < 8; w++) s += sh[w];
        g_A1[i] = s;
    }
}

// ---------------- K4: per-(a,i) scalar s ----------------
__global__ void k_s_kernel() {
    int a = blockIdx.x, i = threadIdx.x;
    // c[a,i] = km_cos[i,a] + mx_cos[i]; km symmetric so read coalesced row a
    float c = g_km[a * MM + i] * g_rnm[i] * g_rnm[a] + g_mx[i];
    float nkp = sqrtf(fmaxf(g_nm2[i] + 2.f * c * g_Sm[i] + (float)DD * c * c,
                            EPSF * EPSF));
    float cos_kp_x = (g_kx[i] + c * g_Sx) / (nkp * g_nx);
    float cnt = g_cnt;
    float mean = (cnt > 0.f) ? (g_A1[i] + c * g_A2) / (nkp * fmaxf(cnt, 1.f)) : 0.f;
    g_s[a * MM + i] = c + cos_kp_x + mean;
}

// ---------------- K5: the streaming broadcast-add (HBM-bound) ----------------
// grid (i=256, a-chunk=8), 192 threads; each thread owns one float4 of the D row.
// mem row stays in registers; inactive rows skip the noise read entirely.
__global__ void k_out(const float4* __restrict__ memv,
                      const float4* __restrict__ noise,
                      float4* __restrict__ out) {
    int i = blockIdx.x;
    int a0 = blockIdx.y << 5;
    int t = threadIdx.x;
    float4 mv = memv[i * 192 + t];
#pragma unroll 4
    for (int a = a0; a < a0 + 32; a++) {
        int base = (a * MM + i) * 192 + t;    // < 2^31, fits int
        float m = g_mask[a];
        if (m != 0.f) {
            float s = g_s[a * MM + i];
            float4 nz = noise[base];
            float4 r;
            r.x = mv.x + s + nz.x;
            r.y = mv.y + s + nz.y;
            r.z = mv.z + s + nz.z;
            r.w = mv.w + s + nz.w;
            out[base] = r;
        } else {
            out[base] = make_float4(0.f, 0.f, 0.f, 0.f);
        }
    }
}

// ---------------- launch ----------------
extern "C" void kernel_launch(void* const* d_in, const int* in_sizes, int n_in,
                              void* d_out, int out_size) {
    const float* x     = (const float*)d_in[0];
    const float* mem   = (const float*)d_in[1];
    const float* noise = (const float*)d_in[2];
    float* out = (float*)d_out;

    k_stats<<<MM + 1, 256>>>(x, mem);
    k_mask_kernel<<<1, 256>>>();
    k_gram<<<dim3(16, 16), 256>>>(mem);
    k_a1<<<MM, 256>>>();
    k_s_kernel<<<MM, 256>>>();
    k_out<<<dim3(MM, 8), 192>>>((const float4*)mem, (const float4*)noise,
                                (float4*)out);
}